// round 8
// baseline (speedup 1.0000x reference)
#include <cuda_runtime.h>
#include <math.h>

#define C_   32
#define C2_  16
#define D_   48
#define H_   128
#define W_   160
#define HW_  (H_*W_)
#define NV_  4

// padded volume dims: (c2, D+2, H+2, Wp)
#define DP_  50
#define HP_  130
#define WP_  168
#define CSTRIDE_ (DP_*HP_*WP_)
#define BORDER_PER_C2_ 108960

// padded channel-last source dims (+2 halo each side)
#define WS_  164
#define HS_  132
#define SPLANE_ (HS_*WS_)

// Scratch (device globals: allocation-free rule)
__device__ float  g_rt[NV_][12];
__device__ __align__(16) float g_srccl[NV_*SPLANE_*C_];  // channel-last padded src
__device__ __align__(16) float g_refcl[NV_*HW_*C_];      // channel-last ref
__device__ float4 g_tap[NV_*D_*HW_];                     // (base_as_float, wx, wy, 0)
__device__ float2 g_volp[C2_*CSTRIDE_];                  // padded volume (c2,d,y,x)
__device__ float  g_cost[D_*HW_];

// ---------------------------------------------------------------------------
// K0: projection algebra (fp64). proj layout: (B=1, V=5, 2, 4, 4).
// ---------------------------------------------------------------------------
__global__ void k_params(const float* __restrict__ proj) {
    if (threadIdx.x != 0 || blockIdx.x != 0) return;

    double Ar[9], ar[3];
    {
        const float* E = proj;
        const float* K = proj + 16;
        for (int i = 0; i < 3; i++) {
            for (int j = 0; j < 3; j++) {
                double s = 0.0;
                for (int k = 0; k < 3; k++) s += (double)K[i*4+k] * (double)E[k*4+j];
                Ar[i*3+j] = s;
            }
            double s = 0.0;
            for (int k = 0; k < 3; k++) s += (double)K[i*4+k] * (double)E[k*4+3];
            ar[i] = s;
        }
    }
    double inv[9];
    double det = Ar[0]*(Ar[4]*Ar[8]-Ar[5]*Ar[7])
               - Ar[1]*(Ar[3]*Ar[8]-Ar[5]*Ar[6])
               + Ar[2]*(Ar[3]*Ar[7]-Ar[4]*Ar[6]);
    double id = 1.0 / det;
    inv[0] = (Ar[4]*Ar[8]-Ar[5]*Ar[7])*id;
    inv[1] = (Ar[2]*Ar[7]-Ar[1]*Ar[8])*id;
    inv[2] = (Ar[1]*Ar[5]-Ar[2]*Ar[4])*id;
    inv[3] = (Ar[5]*Ar[6]-Ar[3]*Ar[8])*id;
    inv[4] = (Ar[0]*Ar[8]-Ar[2]*Ar[6])*id;
    inv[5] = (Ar[2]*Ar[3]-Ar[0]*Ar[5])*id;
    inv[6] = (Ar[3]*Ar[7]-Ar[4]*Ar[6])*id;
    inv[7] = (Ar[1]*Ar[6]-Ar[0]*Ar[7])*id;
    inv[8] = (Ar[0]*Ar[4]-Ar[1]*Ar[3])*id;

    for (int v = 0; v < NV_; v++) {
        const float* E = proj + (v+1)*32;
        const float* K = proj + (v+1)*32 + 16;
        double As[9], as_[3];
        for (int i = 0; i < 3; i++) {
            for (int j = 0; j < 3; j++) {
                double s = 0.0;
                for (int k = 0; k < 3; k++) s += (double)K[i*4+k] * (double)E[k*4+j];
                As[i*3+j] = s;
            }
            double s = 0.0;
            for (int k = 0; k < 3; k++) s += (double)K[i*4+k] * (double)E[k*4+3];
            as_[i] = s;
        }
        double rot[9], tr[3];
        for (int i = 0; i < 3; i++)
            for (int j = 0; j < 3; j++) {
                double s = 0.0;
                for (int k = 0; k < 3; k++) s += As[i*3+k] * inv[k*3+j];
                rot[i*3+j] = s;
            }
        for (int i = 0; i < 3; i++) {
            double s = as_[i];
            for (int k = 0; k < 3; k++) s -= rot[i*3+k] * ar[k];
            tr[i] = s;
        }
        for (int i = 0; i < 9; i++) g_rt[v][i] = (float)rot[i];
        for (int i = 0; i < 3; i++) g_rt[v][9+i] = (float)tr[i];
    }
}

// ---------------------------------------------------------------------------
// Kt: precompute per-(v,d,pix) tap base + fractional weights.
// No masks needed: src is zero-padded; clamped coords keep taps in-bounds
// and out-of-range taps read exact zeros (same result as reference masking).
// ---------------------------------------------------------------------------
__global__ void __launch_bounds__(256) k_tap(const float* __restrict__ depv) {
    int idx = blockIdx.x * 256 + threadIdx.x;
    if (idx >= NV_*D_*HW_) return;
    int v   = idx / (D_*HW_);
    int r   = idx - v*(D_*HW_);
    int d   = r / HW_;
    int pix = r - d*HW_;
    int y   = pix / W_;
    int x   = pix - y*W_;

    const float* rt = g_rt[v];
    float dep = depv[d];
    float fx = (float)x, fy = (float)y;

    float pz  = (rt[6]*fx + rt[7]*fy + rt[8])*dep + rt[11];
    float ipz = 1.0f / pz;
    float px  = ((rt[0]*fx + rt[1]*fy + rt[2])*dep + rt[9])  * ipz;
    float py  = ((rt[3]*fx + rt[4]*fy + rt[5])*dep + rt[10]) * ipz;

    px = fminf(fmaxf(px, -2.f), (float)W_);
    py = fminf(fmaxf(py, -2.f), (float)H_);

    float x0f = floorf(px), y0f = floorf(py);
    float wx = px - x0f,    wy = py - y0f;

    int base = ((int)y0f + 2)*WS_ + (int)x0f + 2;   // padded pixel index
    g_tap[idx] = make_float4(__int_as_float(base), wx, wy, 0.f);
}

// ---------------------------------------------------------------------------
// Kzs: zero the whole channel-last padded src (interior overwritten by k_cvt).
// ---------------------------------------------------------------------------
__global__ void __launch_bounds__(256) k_zsrc() {
    int idx = blockIdx.x * 256 + threadIdx.x;
    if (idx < NV_*SPLANE_*C_/4)
        ((float4*)g_srccl)[idx] = make_float4(0.f, 0.f, 0.f, 0.f);
}

// ---------------------------------------------------------------------------
// Kc: transpose (V,C,H,W) -> channel-last src (padded) + channel-last ref.
// 32x (x) by 32 (c) smem tiles. Exact permutation.
// grid (W/32, H, V), block (32, 8).
// ---------------------------------------------------------------------------
__global__ void __launch_bounds__(256) k_cvt(const float* __restrict__ src,
                                             const float* __restrict__ ref) {
    __shared__ float s_src[C_][33];
    __shared__ float s_ref[C_][33];

    const int tx = threadIdx.x, ty = threadIdx.y;
    const int x0 = blockIdx.x * 32;
    const int y  = blockIdx.y;
    const int v  = blockIdx.z;

#pragma unroll
    for (int cc = 0; cc < 4; cc++) {
        int c = cc*8 + ty;
        size_t a = ((size_t)(v*C_ + c)*H_ + y)*W_ + x0 + tx;
        s_src[c][tx] = src[a];
        s_ref[c][tx] = ref[a];
    }
    __syncthreads();

#pragma unroll
    for (int xx = 0; xx < 4; xx++) {
        int xl = xx*8 + ty;
        int xg = x0 + xl;
        g_srccl[((size_t)v*SPLANE_ + (size_t)(y+2)*WS_ + (xg+2))*C_ + tx] = s_src[tx][xl];
        g_refcl[((size_t)v*HW_ + (size_t)y*W_ + xg)*C_ + tx]             = s_ref[tx][xl];
    }
}

// ---------------------------------------------------------------------------
// Kz: zero the padding border of g_volp (interior written by k_vol).
// ---------------------------------------------------------------------------
__global__ void __launch_bounds__(256) k_zero() {
    int idx = blockIdx.x * 256 + threadIdx.x;
    if (idx >= C2_*BORDER_PER_C2_) return;
    int c2 = idx / BORDER_PER_C2_;
    int t  = idx % BORDER_PER_C2_;
    int dd, yy, xx;
    if (t < 2*HP_*WP_) {
        int sl = t / (HP_*WP_);
        int rr = t % (HP_*WP_);
        dd = sl * (DP_-1);
        yy = rr / WP_;
        xx = rr % WP_;
    } else {
        int r = t - 2*HP_*WP_;
        dd = r / 1360 + 1;
        int s = r % 1360;
        if (s < 2*WP_) {
            yy = (s / WP_) * (HP_-1);
            xx = s % WP_;
        } else {
            int q = s - 2*WP_;
            yy = (q >> 3) + 1;
            int xc = q & 7;
            xx = (xc == 0) ? 0 : (W_ + xc);
        }
    }
    g_volp[(size_t)c2*CSTRIDE_ + ((size_t)dd*HP_ + yy)*WP_ + xx] = make_float2(0.f, 0.f);
}

// ---------------------------------------------------------------------------
// K1: build volume_mean. lane = channel, warp = one pixel, loop over 48 d.
// Every tap load is one 128B-coalesced LDG.32 (1 wavefront, 0 replays).
// Per-(pix,d,v) projection comes precomputed from g_tap (broadcast LDG.128).
// Results transposed through smem into padded (c2,d,y,x) float2 volume.
// ---------------------------------------------------------------------------
__global__ void __launch_bounds__(256) k_vol() {
    __shared__ float sacc[4][8][33];     // [d-chunk][pix][c(padded)]

    const int lane = threadIdx.x;        // channel
    const int wid  = threadIdx.y;        // pixel within block
    const int x    = blockIdx.x*8 + wid;
    const int y    = blockIdx.y;
    const int pix  = y*W_ + x;
    const int tid  = wid*32 + lane;

    // preload ref vector (4 views x this lane's channel)
    float refv[NV_];
#pragma unroll
    for (int v = 0; v < NV_; v++)
        refv[v] = g_refcl[((size_t)v*HW_ + pix)*C_ + lane];

    const int sxi = tid & 7;             // store-phase pixel
    const int sc2 = (tid >> 3) & 15;     // store-phase channel pair
    const int sdi = tid >> 7;            // store-phase d base (0/1)

    for (int dc = 0; dc < 12; dc++) {
#pragma unroll
        for (int di = 0; di < 4; di++) {
            const int d = dc*4 + di;
            float acc = 0.f;
#pragma unroll
            for (int v = 0; v < NV_; v++) {
                float4 tp = __ldg(&g_tap[(v*D_ + d)*HW_ + pix]);
                int   base = __float_as_int(tp.x);
                float wx = tp.y, wy = tp.z;
                const float* S = g_srccl + ((size_t)v*SPLANE_ + base)*C_ + lane;
                float t0 = __ldg(S);
                float t1 = __ldg(S + C_);
                float t2 = __ldg(S + WS_*C_);
                float t3 = __ldg(S + WS_*C_ + C_);
                float w0x = 1.f - wx, w0y = 1.f - wy;
                float s = t0*(w0x*w0y) + t1*(wx*w0y) + t2*(w0x*wy) + t3*(wx*wy);
                acc += refv[v] * s;
            }
            sacc[di][wid][lane] = acc * 0.25f;
        }
        __syncthreads();

        // store phase: 256 threads write 4d x 8pix x 16c2 float2
#pragma unroll
        for (int k = 0; k < 2; k++) {
            int di = sdi + k*2;
            int d  = dc*4 + di;
            float2 val = make_float2(sacc[di][sxi][2*sc2], sacc[di][sxi][2*sc2+1]);
            g_volp[(size_t)sc2*CSTRIDE_ + ((size_t)(d+1)*HP_ + (y+1))*WP_
                   + (blockIdx.x*8 + sxi + 1)] = val;
        }
        __syncthreads();
    }
}

// ---------------------------------------------------------------------------
// K2: 3x3x3 conv via padded volume, d-tile 4. No bounds checks, no div/mod
// in hot loop. Thread owns 4 d-outputs (register sliding window).
// ---------------------------------------------------------------------------
__global__ void __launch_bounds__(256) k_conv(const float* __restrict__ wreg) {
    __shared__ float2 tile[2040];        // [6 d][10 y][34 x]
    __shared__ float2 wsh2[C2_*27];

    const int tx = threadIdx.x, ty = threadIdx.y;
    const int tid = ty*32 + tx;
    const int x0 = blockIdx.x*32, y0 = blockIdx.y*8, d0 = blockIdx.z*4;

    for (int i = tid; i < C2_*27; i += 256) {
        int c2 = i / 27, t = i % 27;
        wsh2[i] = make_float2(wreg[(2*c2)*27 + t], wreg[(2*c2+1)*27 + t]);
    }

    int gOff[8];
#pragma unroll
    for (int k = 0; k < 8; k++) {
        int i = tid + k*256;
        if (i < 2040) {
            int dd = i / 340;
            int r  = i - dd*340;
            int yy = r / 34;
            int xx = r - yy*34;
            gOff[k] = (dd*HP_ + yy)*WP_ + xx;
        } else gOff[k] = 0;
    }
    const size_t base0 = ((size_t)d0*HP_ + y0)*WP_ + x0;

    float accx[4], accy[4];
#pragma unroll
    for (int j = 0; j < 4; j++) { accx[j] = 0.f; accy[j] = 0.f; }

    for (int c2 = 0; c2 < C2_; c2++) {
        __syncthreads();
        const float2* p = g_volp + (size_t)c2*CSTRIDE_ + base0;
#pragma unroll
        for (int k = 0; k < 7; k++)
            tile[tid + k*256] = __ldg(p + gOff[k]);
        if (tid < 2040 - 7*256)
            tile[tid + 7*256] = __ldg(p + gOff[7]);
        __syncthreads();

#pragma unroll
        for (int dy = 0; dy < 3; dy++)
#pragma unroll
        for (int dx = 0; dx < 3; dx++) {
            float2 col[6];
#pragma unroll
            for (int k = 0; k < 6; k++)
                col[k] = tile[k*340 + (ty + dy)*34 + tx + dx];
#pragma unroll
            for (int dz = 0; dz < 3; dz++) {
                float2 w = wsh2[c2*27 + dz*9 + dy*3 + dx];
#pragma unroll
                for (int j = 0; j < 4; j++) {
                    accx[j] += w.x * col[j + dz].x;
                    accy[j] += w.y * col[j + dz].y;
                }
            }
        }
    }

#pragma unroll
    for (int j = 0; j < 4; j++)
        g_cost[(size_t)(d0 + j)*HW_ + (y0 + ty)*W_ + (x0 + tx)] = accx[j] + accy[j];
}

// ---------------------------------------------------------------------------
// K3: softmax over D + expected depth + confidence. Cost cached in registers.
// ---------------------------------------------------------------------------
__global__ void __launch_bounds__(W_) k_post(const float* __restrict__ depv,
                                             float* __restrict__ out) {
    const int x = threadIdx.x;
    const int y = blockIdx.x;
    const int pix = y*W_ + x;

    float cv[D_];
    float m = -1e30f;
#pragma unroll
    for (int d = 0; d < D_; d++) {
        cv[d] = g_cost[(size_t)d*HW_ + pix];
        m = fmaxf(m, cv[d]);
    }

    float s = 0.f, sd = 0.f, sdep = 0.f;
#pragma unroll
    for (int d = 0; d < D_; d++) {
        float e = expf(cv[d] - m);
        s    += e;
        sd   += e * (float)d;
        sdep += e * depv[d];
    }
    float invs = 1.f / s;
    out[pix] = sdep * invs;

    int idx = (int)(sd * invs);
    idx = min(max(idx, 0), D_-1);

    float cw = 0.f;
#pragma unroll
    for (int t = -1; t <= 2; t++) {
        int dd = idx + t;
        if (dd >= 0 && dd < D_)
            cw += expf(cv[dd] - m);
    }
    out[HW_ + pix] = cw * invs;
}

// ---------------------------------------------------------------------------
extern "C" void kernel_launch(void* const* d_in, const int* in_sizes, int n_in,
                              void* d_out, int out_size) {
    const float* ref  = (const float*)d_in[0];
    const float* src  = (const float*)d_in[1];
    const float* proj = (const float*)d_in[2];
    const float* depv = (const float*)d_in[3];

    const float* wreg = (const float*)d_in[n_in - 1];
    for (int i = 4; i < n_in; i++)
        if (in_sizes[i] == C_*27) { wreg = (const float*)d_in[i]; break; }

    float* out = (float*)d_out;

    k_params<<<1, 32>>>(proj);
    k_tap<<<(NV_*D_*HW_ + 255)/256, 256>>>(depv);
    k_zsrc<<<(NV_*SPLANE_*C_/4 + 255)/256, 256>>>();
    k_cvt<<<dim3(W_/32, H_, NV_), dim3(32, 8)>>>(src, ref);
    k_zero<<<(C2_*BORDER_PER_C2_ + 255)/256, 256>>>();
    k_vol<<<dim3(W_/8, H_), dim3(32, 8)>>>();
    k_conv<<<dim3(W_/32, H_/8, D_/4), dim3(32, 8)>>>(wreg);
    k_post<<<H_, W_>>>(depv, out);
}

// round 9
// speedup vs baseline: 1.6614x; 1.6614x over previous
#include <cuda_runtime.h>
#include <math.h>

#define C_   32
#define C2_  16
#define C4_  8
#define D_   48
#define H_   128
#define W_   160
#define HW_  (H_*W_)
#define NV_  4

// padded volume dims: (c2, D+2, H+2, Wp)
#define DP_  50
#define HP_  130
#define WP_  168
#define CSTRIDE_ (DP_*HP_*WP_)
#define BORDER_PER_C2_ 108960

// Scratch (device globals: allocation-free rule)
__device__ float  g_rt[NV_][12];
__device__ float4 g_src4[NV_*C4_*HW_];        // src feats channel-quads
__device__ float4 g_ref4[NV_*C4_*HW_];        // ref feats channel-quads
__device__ float2 g_volp[C2_*CSTRIDE_];       // padded volume_mean
__device__ float  g_cost[D_*HW_];

// ---------------------------------------------------------------------------
// K0: projection algebra (fp64). proj layout: (B=1, V=5, 2, 4, 4).
// ---------------------------------------------------------------------------
__global__ void k_params(const float* __restrict__ proj) {
    if (threadIdx.x != 0 || blockIdx.x != 0) return;

    double Ar[9], ar[3];
    {
        const float* E = proj;
        const float* K = proj + 16;
        for (int i = 0; i < 3; i++) {
            for (int j = 0; j < 3; j++) {
                double s = 0.0;
                for (int k = 0; k < 3; k++) s += (double)K[i*4+k] * (double)E[k*4+j];
                Ar[i*3+j] = s;
            }
            double s = 0.0;
            for (int k = 0; k < 3; k++) s += (double)K[i*4+k] * (double)E[k*4+3];
            ar[i] = s;
        }
    }
    double inv[9];
    double det = Ar[0]*(Ar[4]*Ar[8]-Ar[5]*Ar[7])
               - Ar[1]*(Ar[3]*Ar[8]-Ar[5]*Ar[6])
               + Ar[2]*(Ar[3]*Ar[7]-Ar[4]*Ar[6]);
    double id = 1.0 / det;
    inv[0] = (Ar[4]*Ar[8]-Ar[5]*Ar[7])*id;
    inv[1] = (Ar[2]*Ar[7]-Ar[1]*Ar[8])*id;
    inv[2] = (Ar[1]*Ar[5]-Ar[2]*Ar[4])*id;
    inv[3] = (Ar[5]*Ar[6]-Ar[3]*Ar[8])*id;
    inv[4] = (Ar[0]*Ar[8]-Ar[2]*Ar[6])*id;
    inv[5] = (Ar[2]*Ar[3]-Ar[0]*Ar[5])*id;
    inv[6] = (Ar[3]*Ar[7]-Ar[4]*Ar[6])*id;
    inv[7] = (Ar[1]*Ar[6]-Ar[0]*Ar[7])*id;
    inv[8] = (Ar[0]*Ar[4]-Ar[1]*Ar[3])*id;

    for (int v = 0; v < NV_; v++) {
        const float* E = proj + (v+1)*32;
        const float* K = proj + (v+1)*32 + 16;
        double As[9], as_[3];
        for (int i = 0; i < 3; i++) {
            for (int j = 0; j < 3; j++) {
                double s = 0.0;
                for (int k = 0; k < 3; k++) s += (double)K[i*4+k] * (double)E[k*4+j];
                As[i*3+j] = s;
            }
            double s = 0.0;
            for (int k = 0; k < 3; k++) s += (double)K[i*4+k] * (double)E[k*4+3];
            as_[i] = s;
        }
        double rot[9], tr[3];
        for (int i = 0; i < 3; i++)
            for (int j = 0; j < 3; j++) {
                double s = 0.0;
                for (int k = 0; k < 3; k++) s += As[i*3+k] * inv[k*3+j];
                rot[i*3+j] = s;
            }
        for (int i = 0; i < 3; i++) {
            double s = as_[i];
            for (int k = 0; k < 3; k++) s -= rot[i*3+k] * ar[k];
            tr[i] = s;
        }
        for (int i = 0; i < 9; i++) g_rt[v][i] = (float)rot[i];
        for (int i = 0; i < 3; i++) g_rt[v][9+i] = (float)tr[i];
    }
}

// ---------------------------------------------------------------------------
// Kc: (V,C,H,W) fp32 -> channel-quad float4. Exact permutation.
// ---------------------------------------------------------------------------
__global__ void __launch_bounds__(256) k_cvt(const float* __restrict__ src,
                                             const float* __restrict__ ref) {
    int idx = blockIdx.x * 256 + threadIdx.x;
    if (idx >= NV_*C4_*HW_) return;
    int p   = idx % HW_;
    int vc4 = idx / HW_;
    int v   = vc4 >> 3;
    int c4  = vc4 & 7;
    size_t a = (size_t)(v*C_ + 4*c4) * HW_ + p;
    g_src4[idx] = make_float4(src[a], src[a+HW_], src[a+2*HW_], src[a+3*HW_]);
    g_ref4[idx] = make_float4(ref[a], ref[a+HW_], ref[a+2*HW_], ref[a+3*HW_]);
}

// ---------------------------------------------------------------------------
// Kz: zero the padding border of g_volp (interior written by k_vol).
// ---------------------------------------------------------------------------
__global__ void __launch_bounds__(256) k_zero() {
    int idx = blockIdx.x * 256 + threadIdx.x;
    if (idx >= C2_*BORDER_PER_C2_) return;
    int c2 = idx / BORDER_PER_C2_;
    int t  = idx % BORDER_PER_C2_;
    int dd, yy, xx;
    if (t < 2*HP_*WP_) {                       // d = 0 / 49 full slabs
        int sl = t / (HP_*WP_);
        int rr = t % (HP_*WP_);
        dd = sl * (DP_-1);
        yy = rr / WP_;
        xx = rr % WP_;
    } else {
        int r = t - 2*HP_*WP_;
        dd = r / 1360 + 1;                     // per-d border = 2*168 + 128*8
        int s = r % 1360;
        if (s < 2*WP_) {                       // y = 0 / 129 rows
            yy = (s / WP_) * (HP_-1);
            xx = s % WP_;
        } else {
            int q = s - 2*WP_;
            yy = (q >> 3) + 1;
            int xc = q & 7;
            xx = (xc == 0) ? 0 : (W_ + xc);    // x=0 and x=161..167
        }
    }
    g_volp[(size_t)c2*CSTRIDE_ + ((size_t)dd*HP_ + yy)*WP_ + xx] = make_float2(0.f, 0.f);
}

// ---------------------------------------------------------------------------
// K1: build volume_mean (padded layout). Block = 32 x-pixels x 1 y x 48 d.
// Channel-quad float4 gathers: 128 LDG.128 per (pix,d) instead of 256 LDG.64
// -> lower LSU issue count AND lower total L1 wavefront cycles.
// Tap state: base + dxo + dyo + 4 axis-masked factored weights (round-6 form).
// ---------------------------------------------------------------------------
__global__ void __launch_bounds__(256, 3) k_vol(const float* __restrict__ depv) {
    __shared__ float4 refs[NV_][C4_][32];

    const int tx = threadIdx.x;
    const int dg = threadIdx.y;
    const int tid = dg*32 + tx;
    const int x0 = blockIdx.x * 32;
    const int y  = blockIdx.y;
    const int x  = x0 + tx;

    for (int i = tid; i < NV_*C4_*32; i += 256) {
        int v  = i >> 8;
        int r  = i & 255;
        int c4 = r >> 5;
        int xx = r & 31;
        refs[v][c4][xx] = g_ref4[(v*C4_ + c4)*HW_ + y*W_ + x0 + xx];
    }
    __syncthreads();

    const float fx = (float)x, fy = (float)y;

    for (int i = 0; i < 6; i++) {
        const int d = dg*6 + i;
        const float dep = depv[d];

        int   base[NV_], dxo[NV_], dyo[NV_];
        float wx0[NV_], wx1[NV_], wy0[NV_], wy1[NV_];
#pragma unroll
        for (int v = 0; v < NV_; v++) {
            const float* rt = g_rt[v];
            float pz  = (rt[6]*fx + rt[7]*fy + rt[8])*dep + rt[11];
            float ipz = 1.0f / pz;
            float px  = ((rt[0]*fx + rt[1]*fy + rt[2])*dep + rt[9])  * ipz;
            float py  = ((rt[3]*fx + rt[4]*fy + rt[5])*dep + rt[10]) * ipz;

            float x0f = floorf(px), y0f = floorf(py);
            float wx = px - x0f,    wy = py - y0f;

            bool vx0 = (x0f >=  0.f) && (x0f <= (float)(W_-1));
            bool vx1 = (x0f >= -1.f) && (x0f <= (float)(W_-2));
            bool vy0 = (y0f >=  0.f) && (y0f <= (float)(H_-1));
            bool vy1 = (y0f >= -1.f) && (y0f <= (float)(H_-2));

            int ix0 = min(max((int)x0f,     0), W_-1);
            int ix1 = min(max((int)x0f + 1, 0), W_-1);
            int iy0 = min(max((int)y0f,     0), H_-1);
            int iy1 = min(max((int)y0f + 1, 0), H_-1);

            wx0[v] = vx0 ? (1.f - wx) : 0.f;
            wx1[v] = vx1 ? wx         : 0.f;
            wy0[v] = vy0 ? (1.f - wy) : 0.f;
            wy1[v] = vy1 ? wy         : 0.f;

            base[v] = iy0*W_ + ix0;
            dxo[v]  = ix1 - ix0;           // 0 or 1
            dyo[v]  = (iy1 - iy0)*W_;      // 0 or W_
        }

        float2* dst = g_volp + ((size_t)(d+1)*HP_ + (y+1))*WP_ + (x+1);

        for (int c4 = 0; c4 < C4_; c4++) {
            float a0 = 0.f, a1 = 0.f, a2c = 0.f, a3 = 0.f;
#pragma unroll
            for (int v = 0; v < NV_; v++) {
                const float4* S = g_src4 + (size_t)(v*C4_ + c4) * HW_;
                int o0 = base[v];
                int o1 = o0 + dxo[v];
                int o2 = o0 + dyo[v];
                int o3 = o2 + dxo[v];
                float4 t0 = __ldg(&S[o0]);
                float4 t1 = __ldg(&S[o1]);
                float4 t2 = __ldg(&S[o2]);
                float4 t3 = __ldg(&S[o3]);
                // factored bilinear with axis-masked weights, 4 channels
                float r0 = wy0[v]*(wx0[v]*t0.x + wx1[v]*t1.x) + wy1[v]*(wx0[v]*t2.x + wx1[v]*t3.x);
                float r1 = wy0[v]*(wx0[v]*t0.y + wx1[v]*t1.y) + wy1[v]*(wx0[v]*t2.y + wx1[v]*t3.y);
                float r2 = wy0[v]*(wx0[v]*t0.z + wx1[v]*t1.z) + wy1[v]*(wx0[v]*t2.z + wx1[v]*t3.z);
                float r3 = wy0[v]*(wx0[v]*t0.w + wx1[v]*t1.w) + wy1[v]*(wx0[v]*t2.w + wx1[v]*t3.w);
                float4 rf = refs[v][c4][tx];
                a0 += rf.x * r0;
                a1 += rf.y * r1;
                a2c += rf.z * r2;
                a3 += rf.w * r3;
            }
            dst[(size_t)(2*c4  )*CSTRIDE_] = make_float2(a0*0.25f, a1*0.25f);
            dst[(size_t)(2*c4+1)*CSTRIDE_] = make_float2(a2c*0.25f, a3*0.25f);
        }
    }
}

// ---------------------------------------------------------------------------
// K2: 3x3x3 conv via padded volume, d-tile 4 (grid 960 -> high occ).
// No bounds checks, no div/mod in hot loop. Thread owns 4 d-outputs.
// ---------------------------------------------------------------------------
__global__ void __launch_bounds__(256) k_conv(const float* __restrict__ wreg) {
    __shared__ float2 tile[2040];        // [6 d][10 y][34 x]
    __shared__ float2 wsh2[C2_*27];      // (even,odd) channel weights

    const int tx = threadIdx.x, ty = threadIdx.y;
    const int tid = ty*32 + tx;
    const int x0 = blockIdx.x*32, y0 = blockIdx.y*8, d0 = blockIdx.z*4;

    for (int i = tid; i < C2_*27; i += 256) {
        int c2 = i / 27, t = i % 27;
        wsh2[i] = make_float2(wreg[(2*c2)*27 + t], wreg[(2*c2+1)*27 + t]);
    }

    int gOff[8];
#pragma unroll
    for (int k = 0; k < 8; k++) {
        int i = tid + k*256;
        if (i < 2040) {
            int dd = i / 340;
            int r  = i - dd*340;
            int yy = r / 34;
            int xx = r - yy*34;
            gOff[k] = (dd*HP_ + yy)*WP_ + xx;
        } else gOff[k] = 0;
    }
    const size_t base0 = ((size_t)d0*HP_ + y0)*WP_ + x0;

    float accx[4], accy[4];
#pragma unroll
    for (int j = 0; j < 4; j++) { accx[j] = 0.f; accy[j] = 0.f; }

    for (int c2 = 0; c2 < C2_; c2++) {
        __syncthreads();
        const float2* p = g_volp + (size_t)c2*CSTRIDE_ + base0;
#pragma unroll
        for (int k = 0; k < 7; k++)
            tile[tid + k*256] = __ldg(p + gOff[k]);
        if (tid < 2040 - 7*256)
            tile[tid + 7*256] = __ldg(p + gOff[7]);
        __syncthreads();

#pragma unroll
        for (int dy = 0; dy < 3; dy++)
#pragma unroll
        for (int dx = 0; dx < 3; dx++) {
            float2 col[6];
#pragma unroll
            for (int k = 0; k < 6; k++)
                col[k] = tile[k*340 + (ty + dy)*34 + tx + dx];
#pragma unroll
            for (int dz = 0; dz < 3; dz++) {
                float2 w = wsh2[c2*27 + dz*9 + dy*3 + dx];
#pragma unroll
                for (int j = 0; j < 4; j++) {
                    accx[j] += w.x * col[j + dz].x;
                    accy[j] += w.y * col[j + dz].y;
                }
            }
        }
    }

#pragma unroll
    for (int j = 0; j < 4; j++)
        g_cost[(size_t)(d0 + j)*HW_ + (y0 + ty)*W_ + (x0 + tx)] = accx[j] + accy[j];
}

// ---------------------------------------------------------------------------
// K3: softmax over D + expected depth + confidence. Cost cached in registers.
// ---------------------------------------------------------------------------
__global__ void __launch_bounds__(W_) k_post(const float* __restrict__ depv,
                                             float* __restrict__ out) {
    const int x = threadIdx.x;
    const int y = blockIdx.x;
    const int pix = y*W_ + x;

    float cv[D_];
    float m = -1e30f;
#pragma unroll
    for (int d = 0; d < D_; d++) {
        cv[d] = g_cost[(size_t)d*HW_ + pix];
        m = fmaxf(m, cv[d]);
    }

    float s = 0.f, sd = 0.f, sdep = 0.f;
#pragma unroll
    for (int d = 0; d < D_; d++) {
        float e = expf(cv[d] - m);
        s    += e;
        sd   += e * (float)d;
        sdep += e * depv[d];
    }
    float invs = 1.f / s;
    out[pix] = sdep * invs;

    int idx = (int)(sd * invs);
    idx = min(max(idx, 0), D_-1);

    float cw = 0.f;
#pragma unroll
    for (int t = -1; t <= 2; t++) {
        int dd = idx + t;
        if (dd >= 0 && dd < D_)
            cw += expf(cv[dd] - m);
    }
    out[HW_ + pix] = cw * invs;
}

// ---------------------------------------------------------------------------
extern "C" void kernel_launch(void* const* d_in, const int* in_sizes, int n_in,
                              void* d_out, int out_size) {
    const float* ref  = (const float*)d_in[0];
    const float* src  = (const float*)d_in[1];
    const float* proj = (const float*)d_in[2];
    const float* depv = (const float*)d_in[3];

    const float* wreg = (const float*)d_in[n_in - 1];
    for (int i = 4; i < n_in; i++)
        if (in_sizes[i] == C_*27) { wreg = (const float*)d_in[i]; break; }

    float* out = (float*)d_out;

    k_params<<<1, 32>>>(proj);
    k_cvt<<<(NV_*C4_*HW_ + 255)/256, 256>>>(src, ref);
    k_zero<<<(C2_*BORDER_PER_C2_ + 255)/256, 256>>>();
    k_vol<<<dim3(W_/32, H_), dim3(32, 8)>>>(depv);
    k_conv<<<dim3(W_/32, H_/8, D_/4), dim3(32, 8)>>>(wreg);
    k_post<<<H_, W_>>>(depv, out);
}

// round 10
// speedup vs baseline: 1.8126x; 1.0910x over previous
#include <cuda_runtime.h>
#include <math.h>

#define C_   32
#define C2_  16
#define C4_  8
#define D_   48
#define H_   128
#define W_   160
#define HW_  (H_*W_)
#define NV_  4

// padded volume dims: (c4, D+2, H+2, Wp) float4
#define DP_  50
#define HP_  130
#define WP_  168
#define CSTRIDE_ (DP_*HP_*WP_)
#define BORDER_PER_PLANE_ 108960

// padded source feature dims (+2 halo each side)
#define WS_  164
#define HS_  132
#define SPLANE_ (HS_*WS_)

// Scratch (device globals: allocation-free rule)
__device__ float  g_rt[NV_][12];
__device__ float4 g_src4p[NV_*C4_*SPLANE_];   // src feats channel-quads, padded
__device__ float4 g_ref4[NV_*C4_*HW_];        // ref feats channel-quads
__device__ float4 g_volp4[C4_*CSTRIDE_];      // padded volume_mean, float4
__device__ float  g_cost[D_*HW_];

// ---------------------------------------------------------------------------
// K0: projection algebra (fp64). proj layout: (B=1, V=5, 2, 4, 4).
// ---------------------------------------------------------------------------
__global__ void k_params(const float* __restrict__ proj) {
    if (threadIdx.x != 0 || blockIdx.x != 0) return;

    double Ar[9], ar[3];
    {
        const float* E = proj;
        const float* K = proj + 16;
        for (int i = 0; i < 3; i++) {
            for (int j = 0; j < 3; j++) {
                double s = 0.0;
                for (int k = 0; k < 3; k++) s += (double)K[i*4+k] * (double)E[k*4+j];
                Ar[i*3+j] = s;
            }
            double s = 0.0;
            for (int k = 0; k < 3; k++) s += (double)K[i*4+k] * (double)E[k*4+3];
            ar[i] = s;
        }
    }
    double inv[9];
    double det = Ar[0]*(Ar[4]*Ar[8]-Ar[5]*Ar[7])
               - Ar[1]*(Ar[3]*Ar[8]-Ar[5]*Ar[6])
               + Ar[2]*(Ar[3]*Ar[7]-Ar[4]*Ar[6]);
    double id = 1.0 / det;
    inv[0] = (Ar[4]*Ar[8]-Ar[5]*Ar[7])*id;
    inv[1] = (Ar[2]*Ar[7]-Ar[1]*Ar[8])*id;
    inv[2] = (Ar[1]*Ar[5]-Ar[2]*Ar[4])*id;
    inv[3] = (Ar[5]*Ar[6]-Ar[3]*Ar[8])*id;
    inv[4] = (Ar[0]*Ar[8]-Ar[2]*Ar[6])*id;
    inv[5] = (Ar[2]*Ar[3]-Ar[0]*Ar[5])*id;
    inv[6] = (Ar[3]*Ar[7]-Ar[4]*Ar[6])*id;
    inv[7] = (Ar[1]*Ar[6]-Ar[0]*Ar[7])*id;
    inv[8] = (Ar[0]*Ar[4]-Ar[1]*Ar[3])*id;

    for (int v = 0; v < NV_; v++) {
        const float* E = proj + (v+1)*32;
        const float* K = proj + (v+1)*32 + 16;
        double As[9], as_[3];
        for (int i = 0; i < 3; i++) {
            for (int j = 0; j < 3; j++) {
                double s = 0.0;
                for (int k = 0; k < 3; k++) s += (double)K[i*4+k] * (double)E[k*4+j];
                As[i*3+j] = s;
            }
            double s = 0.0;
            for (int k = 0; k < 3; k++) s += (double)K[i*4+k] * (double)E[k*4+3];
            as_[i] = s;
        }
        double rot[9], tr[3];
        for (int i = 0; i < 3; i++)
            for (int j = 0; j < 3; j++) {
                double s = 0.0;
                for (int k = 0; k < 3; k++) s += As[i*3+k] * inv[k*3+j];
                rot[i*3+j] = s;
            }
        for (int i = 0; i < 3; i++) {
            double s = as_[i];
            for (int k = 0; k < 3; k++) s -= rot[i*3+k] * ar[k];
            tr[i] = s;
        }
        for (int i = 0; i < 9; i++) g_rt[v][i] = (float)rot[i];
        for (int i = 0; i < 3; i++) g_rt[v][9+i] = (float)tr[i];
    }
}

// ---------------------------------------------------------------------------
// Kzs: zero the whole padded channel-quad src (interior overwritten by k_cvt).
// ---------------------------------------------------------------------------
__global__ void __launch_bounds__(256) k_zsrc() {
    int idx = blockIdx.x * 256 + threadIdx.x;
    if (idx < NV_*C4_*SPLANE_)
        g_src4p[idx] = make_float4(0.f, 0.f, 0.f, 0.f);
}

// ---------------------------------------------------------------------------
// Kc: (V,C,H,W) fp32 -> channel-quad float4: padded src + ref. Exact.
// ---------------------------------------------------------------------------
__global__ void __launch_bounds__(256) k_cvt(const float* __restrict__ src,
                                             const float* __restrict__ ref) {
    int idx = blockIdx.x * 256 + threadIdx.x;
    if (idx >= NV_*C4_*HW_) return;
    int p   = idx % HW_;
    int vc4 = idx / HW_;
    int v   = vc4 >> 3;
    int c4  = vc4 & 7;
    int y   = p / W_;
    int x   = p - y*W_;
    size_t a = (size_t)(v*C_ + 4*c4) * HW_ + p;
    float4 sv = make_float4(src[a], src[a+HW_], src[a+2*HW_], src[a+3*HW_]);
    g_src4p[(size_t)vc4*SPLANE_ + (size_t)(y+2)*WS_ + (x+2)] = sv;
    g_ref4[idx] = make_float4(ref[a], ref[a+HW_], ref[a+2*HW_], ref[a+3*HW_]);
}

// ---------------------------------------------------------------------------
// Kz: zero the padding border of g_volp4 (interior written by k_vol).
// ---------------------------------------------------------------------------
__global__ void __launch_bounds__(256) k_zero() {
    int idx = blockIdx.x * 256 + threadIdx.x;
    if (idx >= C4_*BORDER_PER_PLANE_) return;
    int c4 = idx / BORDER_PER_PLANE_;
    int t  = idx % BORDER_PER_PLANE_;
    int dd, yy, xx;
    if (t < 2*HP_*WP_) {                       // d = 0 / 49 full slabs
        int sl = t / (HP_*WP_);
        int rr = t % (HP_*WP_);
        dd = sl * (DP_-1);
        yy = rr / WP_;
        xx = rr % WP_;
    } else {
        int r = t - 2*HP_*WP_;
        dd = r / 1360 + 1;                     // per-d border = 2*168 + 128*8
        int s = r % 1360;
        if (s < 2*WP_) {                       // y = 0 / 129 rows
            yy = (s / WP_) * (HP_-1);
            xx = s % WP_;
        } else {
            int q = s - 2*WP_;
            yy = (q >> 3) + 1;
            int xc = q & 7;
            xx = (xc == 0) ? 0 : (W_ + xc);    // x=0 and x=161..167
        }
    }
    g_volp4[(size_t)c4*CSTRIDE_ + ((size_t)dd*HP_ + yy)*WP_ + xx]
        = make_float4(0.f, 0.f, 0.f, 0.f);
}

// ---------------------------------------------------------------------------
// K1: build volume_mean (padded float4 layout). Block = 32 x-px x 1 y x 48 d.
// Padded src: taps at base, base+1, base+WS, base+WS+1 -- no int clamps.
// Axis-masked factored weights reproduce reference masking exactly.
// 8 STG.128 per (pix,d) instead of 16 STG.64.
// ---------------------------------------------------------------------------
__global__ void __launch_bounds__(256, 3) k_vol(const float* __restrict__ depv) {
    __shared__ float4 refs[NV_][C4_][32];

    const int tx = threadIdx.x;
    const int dg = threadIdx.y;
    const int tid = dg*32 + tx;
    const int x0 = blockIdx.x * 32;
    const int y  = blockIdx.y;
    const int x  = x0 + tx;

    for (int i = tid; i < NV_*C4_*32; i += 256) {
        int v  = i >> 8;
        int r  = i & 255;
        int c4 = r >> 5;
        int xx = r & 31;
        refs[v][c4][xx] = g_ref4[(v*C4_ + c4)*HW_ + y*W_ + x0 + xx];
    }
    __syncthreads();

    const float fx = (float)x, fy = (float)y;

    for (int i = 0; i < 6; i++) {
        const int d = dg*6 + i;
        const float dep = depv[d];

        int   base[NV_];
        float wx0[NV_], wx1[NV_], wy0[NV_], wy1[NV_];
#pragma unroll
        for (int v = 0; v < NV_; v++) {
            const float* rt = g_rt[v];
            float pz  = (rt[6]*fx + rt[7]*fy + rt[8])*dep + rt[11];
            float ipz = 1.0f / pz;
            float px  = ((rt[0]*fx + rt[1]*fy + rt[2])*dep + rt[9])  * ipz;
            float py  = ((rt[3]*fx + rt[4]*fy + rt[5])*dep + rt[10]) * ipz;

            // clamp into padded-address-safe range; weights mask the rest
            px = fminf(fmaxf(px, -2.f), (float)W_);
            py = fminf(fmaxf(py, -2.f), (float)H_);

            float x0f = floorf(px), y0f = floorf(py);
            float wx = px - x0f,    wy = py - y0f;

            bool vx0 = (x0f >=  0.f) && (x0f <= (float)(W_-1));
            bool vx1 = (x0f >= -1.f) && (x0f <= (float)(W_-2));
            bool vy0 = (y0f >=  0.f) && (y0f <= (float)(H_-1));
            bool vy1 = (y0f >= -1.f) && (y0f <= (float)(H_-2));

            wx0[v] = vx0 ? (1.f - wx) : 0.f;
            wx1[v] = vx1 ? wx         : 0.f;
            wy0[v] = vy0 ? (1.f - wy) : 0.f;
            wy1[v] = vy1 ? wy         : 0.f;

            base[v] = ((int)y0f + 2)*WS_ + (int)x0f + 2;
        }

        float4* dst = g_volp4 + ((size_t)(d+1)*HP_ + (y+1))*WP_ + (x+1);

        for (int c4 = 0; c4 < C4_; c4++) {
            float a0 = 0.f, a1 = 0.f, a2 = 0.f, a3 = 0.f;
#pragma unroll
            for (int v = 0; v < NV_; v++) {
                const float4* S = g_src4p + (size_t)(v*C4_ + c4)*SPLANE_ + base[v];
                float4 t0 = __ldg(S);
                float4 t1 = __ldg(S + 1);
                float4 t2 = __ldg(S + WS_);
                float4 t3 = __ldg(S + WS_ + 1);
                float r0 = wy0[v]*(wx0[v]*t0.x + wx1[v]*t1.x) + wy1[v]*(wx0[v]*t2.x + wx1[v]*t3.x);
                float r1 = wy0[v]*(wx0[v]*t0.y + wx1[v]*t1.y) + wy1[v]*(wx0[v]*t2.y + wx1[v]*t3.y);
                float r2 = wy0[v]*(wx0[v]*t0.z + wx1[v]*t1.z) + wy1[v]*(wx0[v]*t2.z + wx1[v]*t3.z);
                float r3 = wy0[v]*(wx0[v]*t0.w + wx1[v]*t1.w) + wy1[v]*(wx0[v]*t2.w + wx1[v]*t3.w);
                float4 rf = refs[v][c4][tx];
                a0 += rf.x * r0;
                a1 += rf.y * r1;
                a2 += rf.z * r2;
                a3 += rf.w * r3;
            }
            dst[(size_t)c4*CSTRIDE_] =
                make_float4(a0*0.25f, a1*0.25f, a2*0.25f, a3*0.25f);
        }
    }
}

// ---------------------------------------------------------------------------
// K2: 3x3x3 conv via padded float4 volume, d-tile 4. No bounds checks, no
// div/mod in hot loop. Thread owns 4 d-outputs. float4 tiles & weights.
// ---------------------------------------------------------------------------
__global__ void __launch_bounds__(256) k_conv(const float* __restrict__ wreg) {
    __shared__ float4 tile[2040];        // [6 d][10 y][34 x]
    __shared__ float4 wsh4[C4_*27];      // 4-channel packed weights

    const int tx = threadIdx.x, ty = threadIdx.y;
    const int tid = ty*32 + tx;
    const int x0 = blockIdx.x*32, y0 = blockIdx.y*8, d0 = blockIdx.z*4;

    for (int i = tid; i < C4_*27; i += 256) {
        int c4 = i / 27, t = i % 27;
        wsh4[i] = make_float4(wreg[(4*c4  )*27 + t], wreg[(4*c4+1)*27 + t],
                              wreg[(4*c4+2)*27 + t], wreg[(4*c4+3)*27 + t]);
    }

    int gOff[8];
#pragma unroll
    for (int k = 0; k < 8; k++) {
        int i = tid + k*256;
        if (i < 2040) {
            int dd = i / 340;
            int r  = i - dd*340;
            int yy = r / 34;
            int xx = r - yy*34;
            gOff[k] = (dd*HP_ + yy)*WP_ + xx;
        } else gOff[k] = 0;
    }
    const size_t base0 = ((size_t)d0*HP_ + y0)*WP_ + x0;

    float a0[4], a1[4], a2[4], a3[4];
#pragma unroll
    for (int j = 0; j < 4; j++) { a0[j]=0.f; a1[j]=0.f; a2[j]=0.f; a3[j]=0.f; }

    for (int c4 = 0; c4 < C4_; c4++) {
        __syncthreads();
        const float4* p = g_volp4 + (size_t)c4*CSTRIDE_ + base0;
#pragma unroll
        for (int k = 0; k < 7; k++)
            tile[tid + k*256] = __ldg(p + gOff[k]);
        if (tid < 2040 - 7*256)
            tile[tid + 7*256] = __ldg(p + gOff[7]);
        __syncthreads();

#pragma unroll
        for (int dy = 0; dy < 3; dy++)
#pragma unroll
        for (int dx = 0; dx < 3; dx++) {
            float4 col[6];
#pragma unroll
            for (int k = 0; k < 6; k++)
                col[k] = tile[k*340 + (ty + dy)*34 + tx + dx];
#pragma unroll
            for (int dz = 0; dz < 3; dz++) {
                float4 w = wsh4[c4*27 + dz*9 + dy*3 + dx];
#pragma unroll
                for (int j = 0; j < 4; j++) {
                    a0[j] += w.x * col[j + dz].x;
                    a1[j] += w.y * col[j + dz].y;
                    a2[j] += w.z * col[j + dz].z;
                    a3[j] += w.w * col[j + dz].w;
                }
            }
        }
    }

#pragma unroll
    for (int j = 0; j < 4; j++)
        g_cost[(size_t)(d0 + j)*HW_ + (y0 + ty)*W_ + (x0 + tx)]
            = (a0[j] + a1[j]) + (a2[j] + a3[j]);
}

// ---------------------------------------------------------------------------
// K3: softmax over D + expected depth + confidence. Cost cached in registers.
// ---------------------------------------------------------------------------
__global__ void __launch_bounds__(W_) k_post(const float* __restrict__ depv,
                                             float* __restrict__ out) {
    const int x = threadIdx.x;
    const int y = blockIdx.x;
    const int pix = y*W_ + x;

    float cv[D_];
    float m = -1e30f;
#pragma unroll
    for (int d = 0; d < D_; d++) {
        cv[d] = g_cost[(size_t)d*HW_ + pix];
        m = fmaxf(m, cv[d]);
    }

    float s = 0.f, sd = 0.f, sdep = 0.f;
#pragma unroll
    for (int d = 0; d < D_; d++) {
        float e = expf(cv[d] - m);
        s    += e;
        sd   += e * (float)d;
        sdep += e * depv[d];
    }
    float invs = 1.f / s;
    out[pix] = sdep * invs;

    int idx = (int)(sd * invs);
    idx = min(max(idx, 0), D_-1);

    float cw = 0.f;
#pragma unroll
    for (int t = -1; t <= 2; t++) {
        int dd = idx + t;
        if (dd >= 0 && dd < D_)
            cw += expf(cv[dd] - m);
    }
    out[HW_ + pix] = cw * invs;
}

// ---------------------------------------------------------------------------
extern "C" void kernel_launch(void* const* d_in, const int* in_sizes, int n_in,
                              void* d_out, int out_size) {
    const float* ref  = (const float*)d_in[0];
    const float* src  = (const float*)d_in[1];
    const float* proj = (const float*)d_in[2];
    const float* depv = (const float*)d_in[3];

    const float* wreg = (const float*)d_in[n_in - 1];
    for (int i = 4; i < n_in; i++)
        if (in_sizes[i] == C_*27) { wreg = (const float*)d_in[i]; break; }

    float* out = (float*)d_out;

    k_params<<<1, 32>>>(proj);
    k_zsrc<<<(NV_*C4_*SPLANE_ + 255)/256, 256>>>();
    k_cvt<<<(NV_*C4_*HW_ + 255)/256, 256>>>(src, ref);
    k_zero<<<(C4_*BORDER_PER_PLANE_ + 255)/256, 256>>>();
    k_vol<<<dim3(W_/32, H_), dim3(32, 8)>>>(depv);
    k_conv<<<dim3(W_/32, H_/8, D_/4), dim3(32, 8)>>>(wreg);
    k_post<<<H_, W_>>>(depv, out);
}